// round 1
// baseline (speedup 1.0000x reference)
#include <cuda_runtime.h>
#include <math.h>

// Problem constants (LightSS2D: B=2, H=W=96, d_model=96, expand=2)
#define Bsz   2
#define Lseq  9216            // H*W
#define Dm    96
#define Din   192             // d_inner
#define Nst   16              // d_state
#define NCH   36              // scan chunks per batch
#define LCH   256             // chunk length (36*256 = 9216)
#define Mrows (Bsz*Lseq)      // 18432

// ---------------- scratch (device globals; no allocation allowed) ----------
__device__ float g_xz[(size_t)Mrows*384];     // xz = u @ W_in^T  (xs | z)
__device__ float g_xc[(size_t)Mrows*Din];     // silu(conv(xs))
__device__ float g_Bm[(size_t)Mrows*Nst];
__device__ float g_Cm[(size_t)Mrows*Nst];
__device__ float g_delta[(size_t)Mrows*Din];
__device__ float g_y[(size_t)Mrows*Din];      // gated scan output
__device__ float g_Wcat[224*192];             // [B(16); C(16); W_dt@W_x[:6] (192)]
__device__ float g_P[Bsz*NCH*Din*Nst];
__device__ float g_S[Bsz*NCH*Din*Nst];
__device__ float g_h0[Bsz*NCH*Din*Nst];

// ---------------- GEMM: C[M,N] = A[M,K] * B[N,K]^T (both row-major) --------
#define BM 64
#define BN 64
#define BK 16

__device__ __forceinline__ float softplus_f(float v) {
    return (v > 20.f) ? v : log1pf(__expf(v));
}

// MODE 0: A=x (arg), B=W_in (arg), C -> g_xz
// MODE 1: A=g_xc,    B=g_Wcat,     C -> split into g_Bm/g_Cm/g_delta (softplus+b_dt)
// MODE 2: A=g_y,     B=W_out(arg), C -> d_out (arg)
template<int MODE>
__global__ void __launch_bounds__(256) gemm_k(
    const float* __restrict__ Aarg, const float* __restrict__ Barg,
    const float* __restrict__ bias, float* __restrict__ Carg,
    int M, int N, int K)
{
    const float* A    = (MODE == 1) ? g_xc : ((MODE == 2) ? g_y : Aarg);
    const float* Bmat = (MODE == 1) ? g_Wcat : Barg;

    __shared__ float As[BM][BK];
    __shared__ float Bs[BK][BN + 1];

    int tid = threadIdx.x;
    int tx = tid & 15, ty = tid >> 4;
    int m0 = blockIdx.y * BM;
    int n0 = blockIdx.x * BN;

    float acc[4][4] = {};

    for (int k0 = 0; k0 < K; k0 += BK) {
        #pragma unroll
        for (int i = 0; i < 4; i++) {
            int idx = tid + i * 256;
            int mm = idx >> 4;
            int kk = idx & 15;
            As[mm][kk] = A[(size_t)(m0 + mm) * K + k0 + kk];
        }
        #pragma unroll
        for (int i = 0; i < 4; i++) {
            int idx = tid + i * 256;
            int cc = idx >> 4;
            int kk = idx & 15;
            float v = 0.f;
            if (n0 + cc < N) v = Bmat[(size_t)(n0 + cc) * K + k0 + kk];
            Bs[kk][cc] = v;
        }
        __syncthreads();
        #pragma unroll
        for (int k = 0; k < BK; k++) {
            float a[4], b[4];
            #pragma unroll
            for (int i = 0; i < 4; i++) a[i] = As[ty * 4 + i][k];
            #pragma unroll
            for (int j = 0; j < 4; j++) b[j] = Bs[k][tx * 4 + j];
            #pragma unroll
            for (int i = 0; i < 4; i++)
                #pragma unroll
                for (int j = 0; j < 4; j++)
                    acc[i][j] = fmaf(a[i], b[j], acc[i][j]);
        }
        __syncthreads();
    }

    #pragma unroll
    for (int i = 0; i < 4; i++) {
        int row = m0 + ty * 4 + i;
        #pragma unroll
        for (int j = 0; j < 4; j++) {
            int col = n0 + tx * 4 + j;
            if (col >= N) continue;
            float v = acc[i][j];
            if (MODE == 1) {
                if (col < 16)       g_Bm[(size_t)row * 16 + col] = v;
                else if (col < 32)  g_Cm[(size_t)row * 16 + col - 16] = v;
                else                g_delta[(size_t)row * 192 + col - 32] =
                                        softplus_f(v + bias[col - 32]);
            } else if (MODE == 0) {
                g_xz[(size_t)row * 384 + col] = v;
            } else {
                Carg[(size_t)row * N + col] = v;
            }
        }
    }
}

// ---------------- causal depthwise conv (d_conv=3) + SiLU ------------------
__global__ void conv_silu_k(const float* __restrict__ conv_w,
                            const float* __restrict__ conv_b)
{
    int idx = blockIdx.x * blockDim.x + threadIdx.x;
    if (idx >= Mrows * Din) return;
    int d = idx % Din;
    int r = idx / Din;          // b*L + l
    int l = r % Lseq;
    float w0 = conv_w[d * 3 + 0], w1 = conv_w[d * 3 + 1], w2 = conv_w[d * 3 + 2];
    float s = conv_b[d] + g_xz[(size_t)r * 384 + d] * w2;
    if (l >= 1) s += g_xz[(size_t)(r - 1) * 384 + d] * w1;
    if (l >= 2) s += g_xz[(size_t)(r - 2) * 384 + d] * w0;
    g_xc[idx] = s / (1.f + __expf(-s));   // silu
}

// ---------------- build concatenated projection weight ---------------------
// rows 0..15  : W_x rows 6..21   (B)
// rows 16..31 : W_x rows 22..37  (C)
// rows 32..223: (W_dt @ W_x[0:6]) -> pre-softplus delta projection
__global__ void build_wcat_k(const float* __restrict__ W_x,
                             const float* __restrict__ W_dt)
{
    int idx = blockIdx.x * blockDim.x + threadIdx.x;
    if (idx >= 224 * 192) return;
    int r = idx / 192, k = idx % 192;
    float v;
    if (r < 32) {
        v = W_x[(6 + r) * 192 + k];
    } else {
        v = 0.f;
        #pragma unroll
        for (int j = 0; j < 6; j++)
            v = fmaf(W_dt[(r - 32) * 6 + j], W_x[j * 192 + k], v);
    }
    g_Wcat[idx] = v;
}

// ---------------- chunked associative scan ---------------------------------
// thread id layout: tid = ((b*NCH + c)*Din + d)*16 + n   (n in low 4 bits)

__global__ void scan1_k(const float* __restrict__ A_log)
{
    int tid = blockIdx.x * blockDim.x + threadIdx.x;
    const int TOT = Bsz * NCH * Din * Nst;
    if (tid >= TOT) return;
    int n = tid & 15;
    int d = (tid >> 4) % Din;
    int c = (tid / (Nst * Din)) % NCH;
    int b = tid / (Nst * Din * NCH);

    float Aneg = -__expf(A_log[d * Nst + n]);
    int rbase = b * Lseq + c * LCH;
    float h = 0.f, p = 1.f;
    #pragma unroll 4
    for (int t = 0; t < LCH; t++) {
        int r = rbase + t;
        float a  = g_delta[(size_t)r * Din + d];
        float x  = g_xc[(size_t)r * Din + d];
        float Bv = g_Bm[(size_t)r * Nst + n];
        float dA = __expf(a * Aneg);
        p *= dA;
        h = fmaf(dA, h, a * Bv * x);
    }
    g_P[tid] = p;
    g_S[tid] = h;
}

__global__ void scan2_k()
{
    int tid = blockIdx.x * blockDim.x + threadIdx.x;
    if (tid >= Bsz * Din * Nst) return;
    int n = tid & 15;
    int d = (tid >> 4) % Din;
    int b = tid / (Nst * Din);
    float h = 0.f;
    for (int c = 0; c < NCH; c++) {
        int idx = ((b * NCH + c) * Din + d) * Nst + n;
        g_h0[idx] = h;
        h = fmaf(g_P[idx], h, g_S[idx]);
    }
}

__global__ void scan3_k(const float* __restrict__ A_log,
                        const float* __restrict__ Dvec)
{
    int tid = blockIdx.x * blockDim.x + threadIdx.x;
    const int TOT = Bsz * NCH * Din * Nst;
    if (tid >= TOT) return;
    int n = tid & 15;
    int d = (tid >> 4) % Din;
    int c = (tid / (Nst * Din)) % NCH;
    int b = tid / (Nst * Din * NCH);

    float Aneg = -__expf(A_log[d * Nst + n]);
    float h = g_h0[tid];
    float Dd = Dvec[d];
    int rbase = b * Lseq + c * LCH;

    for (int t = 0; t < LCH; t++) {
        int r = rbase + t;
        float a  = g_delta[(size_t)r * Din + d];
        float x  = g_xc[(size_t)r * Din + d];
        float Bv = g_Bm[(size_t)r * Nst + n];
        float Cv = g_Cm[(size_t)r * Nst + n];
        float dA = __expf(a * Aneg);
        h = fmaf(dA, h, a * Bv * x);
        float p = h * Cv;
        // reduce over 16 states (lanes 0-15 / 16-31 are independent channels)
        p += __shfl_xor_sync(0xffffffffu, p, 8);
        p += __shfl_xor_sync(0xffffffffu, p, 4);
        p += __shfl_xor_sync(0xffffffffu, p, 2);
        p += __shfl_xor_sync(0xffffffffu, p, 1);
        if (n == 0) {
            float z = g_xz[(size_t)r * 384 + 192 + d];
            float yy = p + x * Dd;
            g_y[(size_t)r * Din + d] = yy * (z / (1.f + __expf(-z)));
        }
    }
}

// ---------------- launch ----------------------------------------------------
extern "C" void kernel_launch(void* const* d_in, const int* in_sizes, int n_in,
                              void* d_out, int out_size)
{
    const float* x      = (const float*)d_in[0];
    const float* W_in   = (const float*)d_in[1];
    const float* conv_w = (const float*)d_in[2];
    const float* conv_b = (const float*)d_in[3];
    const float* W_x    = (const float*)d_in[4];
    const float* W_dt   = (const float*)d_in[5];
    const float* b_dt   = (const float*)d_in[6];
    const float* A_log  = (const float*)d_in[7];
    const float* Dvec   = (const float*)d_in[8];
    const float* W_out  = (const float*)d_in[9];
    float* out = (float*)d_out;

    // 1) xz = u @ W_in^T   (M=18432, N=384, K=96)
    gemm_k<0><<<dim3(384 / BN, Mrows / BM), 256>>>(x, W_in, nullptr, nullptr,
                                                   Mrows, 384, 96);
    // 2) xc = silu(causal depthwise conv(xs) + b)
    conv_silu_k<<<(Mrows * Din + 255) / 256, 256>>>(conv_w, conv_b);
    // 3) fused projection weight
    build_wcat_k<<<(224 * 192 + 255) / 256, 256>>>(W_x, W_dt);
    // 4) [B | C | delta_pre] = xc @ Wcat^T ; epilogue splits + softplus
    gemm_k<1><<<dim3((224 + BN - 1) / BN, Mrows / BM), 256>>>(
        nullptr, nullptr, b_dt, nullptr, Mrows, 224, 192);
    // 5-7) chunked selective scan (+ D skip + z gate fused in pass 3)
    scan1_k<<<(Bsz * NCH * Din * Nst) / 256, 256>>>(A_log);
    scan2_k<<<(Bsz * Din * Nst + 255) / 256, 256>>>();
    scan3_k<<<(Bsz * NCH * Din * Nst) / 256, 256>>>(A_log, Dvec);
    // 8) out = y @ W_out^T  (N=96, K=192)
    gemm_k<2><<<dim3((96 + BN - 1) / BN, Mrows / BM), 256>>>(
        nullptr, W_out, nullptr, out, Mrows, 96, 192);
}

// round 2
// speedup vs baseline: 1.1783x; 1.1783x over previous
#include <cuda_runtime.h>
#include <math.h>

// Problem constants (LightSS2D: B=2, H=W=96, d_model=96, expand=2)
#define Bsz   2
#define Lseq  9216            // H*W
#define Dm    96
#define Din   192             // d_inner
#define Nst   16              // d_state
#define NCH   36              // scan chunks per batch
#define LCH   256             // chunk length (36*256 = 9216)
#define Mrows (Bsz*Lseq)      // 18432

// ---------------- scratch (device globals; no allocation allowed) ----------
__device__ float g_xz[(size_t)Mrows*384];     // xz = u @ W_in^T  (xs | z)
__device__ float g_xc[(size_t)Mrows*Din];     // silu(conv(xs))
__device__ float g_Bm[(size_t)Mrows*Nst];
__device__ float g_Cm[(size_t)Mrows*Nst];
__device__ float g_delta[(size_t)Mrows*Din];
__device__ float g_y[(size_t)Mrows*Din];      // gated scan output
__device__ float g_Wcat[224*192];             // [B(16); C(16); W_dt@W_x[:6] (192)]
__device__ float g_P[Bsz*NCH*Din*Nst];
__device__ float g_S[Bsz*NCH*Din*Nst];
__device__ float g_h0[Bsz*NCH*Din*Nst];

__device__ __forceinline__ float softplus_f(float v) {
    return (v > 20.f) ? v : log1pf(__expf(v));
}

// ---------------- GEMM: C[M,N] = A[M,K] * B[N,K]^T (both row-major) --------
// 128x128x8 tile, 256 threads, 8x8 micro-tile, float4 vectorized.
#define GBM 128
#define GBN 128
#define GBK 8

// MODE 0: A=x (arg), B=W_in (arg), C -> g_xz
// MODE 1: A=g_xc,    B=g_Wcat,     C -> split into g_Bm/g_Cm/g_delta (softplus+b_dt)
// MODE 2: A=g_y,     B=W_out(arg), C -> d_out (arg)
template<int MODE>
__global__ void __launch_bounds__(256) gemm_k(
    const float* __restrict__ Aarg, const float* __restrict__ Barg,
    const float* __restrict__ bias, float* __restrict__ Carg,
    int M, int N, int K)
{
    const float* A    = (MODE == 1) ? g_xc : ((MODE == 2) ? g_y : Aarg);
    const float* Bmat = (MODE == 1) ? g_Wcat : Barg;

    __shared__ float As[GBK][GBM];
    __shared__ float Bs[GBK][GBN];

    const int tid = threadIdx.x;
    const int tx = tid & 15, ty = tid >> 4;
    const int m0 = blockIdx.y * GBM;
    const int n0 = blockIdx.x * GBN;

    const int lrow = tid >> 1;        // 0..127
    const int lk4  = (tid & 1) * 4;   // 0 or 4

    const bool bload_ok = (n0 + lrow) < N;

    float acc[8][8];
    #pragma unroll
    for (int i = 0; i < 8; i++)
        #pragma unroll
        for (int j = 0; j < 8; j++) acc[i][j] = 0.f;

    for (int k0 = 0; k0 < K; k0 += GBK) {
        float4 av = *(const float4*)&A[(size_t)(m0 + lrow) * K + k0 + lk4];
        float4 bv = make_float4(0.f, 0.f, 0.f, 0.f);
        if (bload_ok)
            bv = *(const float4*)&Bmat[(size_t)(n0 + lrow) * K + k0 + lk4];

        __syncthreads();   // previous iteration's reads complete
        As[lk4 + 0][lrow] = av.x;
        As[lk4 + 1][lrow] = av.y;
        As[lk4 + 2][lrow] = av.z;
        As[lk4 + 3][lrow] = av.w;
        Bs[lk4 + 0][lrow] = bv.x;
        Bs[lk4 + 1][lrow] = bv.y;
        Bs[lk4 + 2][lrow] = bv.z;
        Bs[lk4 + 3][lrow] = bv.w;
        __syncthreads();

        #pragma unroll
        for (int k = 0; k < GBK; k++) {
            float4 a0 = *(const float4*)&As[k][ty * 4];
            float4 a1 = *(const float4*)&As[k][ty * 4 + 64];
            float4 b0 = *(const float4*)&Bs[k][tx * 4];
            float4 b1 = *(const float4*)&Bs[k][tx * 4 + 64];
            float a[8] = {a0.x, a0.y, a0.z, a0.w, a1.x, a1.y, a1.z, a1.w};
            float b[8] = {b0.x, b0.y, b0.z, b0.w, b1.x, b1.y, b1.z, b1.w};
            #pragma unroll
            for (int i = 0; i < 8; i++)
                #pragma unroll
                for (int j = 0; j < 8; j++)
                    acc[i][j] = fmaf(a[i], b[j], acc[i][j]);
        }
    }

    #pragma unroll
    for (int i = 0; i < 8; i++) {
        int row = m0 + ty * 4 + ((i < 4) ? i : (64 + i - 4));
        #pragma unroll
        for (int j = 0; j < 8; j++) {
            int col = n0 + tx * 4 + ((j < 4) ? j : (64 + j - 4));
            if (col >= N) continue;
            float v = acc[i][j];
            if (MODE == 1) {
                if (col < 16)       g_Bm[(size_t)row * 16 + col] = v;
                else if (col < 32)  g_Cm[(size_t)row * 16 + col - 16] = v;
                else                g_delta[(size_t)row * 192 + col - 32] =
                                        softplus_f(v + bias[col - 32]);
            } else if (MODE == 0) {
                g_xz[(size_t)row * 384 + col] = v;
            } else {
                Carg[(size_t)row * N + col] = v;
            }
        }
    }
}

// ---------------- causal depthwise conv (d_conv=3) + SiLU ------------------
__global__ void conv_silu_k(const float* __restrict__ conv_w,
                            const float* __restrict__ conv_b)
{
    int idx = blockIdx.x * blockDim.x + threadIdx.x;
    if (idx >= Mrows * Din) return;
    int d = idx % Din;
    int r = idx / Din;          // b*L + l
    int l = r % Lseq;
    float w0 = conv_w[d * 3 + 0], w1 = conv_w[d * 3 + 1], w2 = conv_w[d * 3 + 2];
    float s = conv_b[d] + g_xz[(size_t)r * 384 + d] * w2;
    if (l >= 1) s += g_xz[(size_t)(r - 1) * 384 + d] * w1;
    if (l >= 2) s += g_xz[(size_t)(r - 2) * 384 + d] * w0;
    g_xc[idx] = s / (1.f + __expf(-s));   // silu
}

// ---------------- build concatenated projection weight ---------------------
__global__ void build_wcat_k(const float* __restrict__ W_x,
                             const float* __restrict__ W_dt)
{
    int idx = blockIdx.x * blockDim.x + threadIdx.x;
    if (idx >= 224 * 192) return;
    int r = idx / 192, k = idx % 192;
    float v;
    if (r < 32) {
        v = W_x[(6 + r) * 192 + k];
    } else {
        v = 0.f;
        #pragma unroll
        for (int j = 0; j < 6; j++)
            v = fmaf(W_dt[(r - 32) * 6 + j], W_x[j * 192 + k], v);
    }
    g_Wcat[idx] = v;
}

// ---------------- chunked associative scan ---------------------------------
__global__ void scan1_k(const float* __restrict__ A_log)
{
    int tid = blockIdx.x * blockDim.x + threadIdx.x;
    const int TOT = Bsz * NCH * Din * Nst;
    if (tid >= TOT) return;
    int n = tid & 15;
    int d = (tid >> 4) % Din;
    int c = (tid / (Nst * Din)) % NCH;
    int b = tid / (Nst * Din * NCH);

    float Aneg = -__expf(A_log[d * Nst + n]);
    int rbase = b * Lseq + c * LCH;
    float h = 0.f, p = 1.f;
    #pragma unroll 4
    for (int t = 0; t < LCH; t++) {
        int r = rbase + t;
        float a  = g_delta[(size_t)r * Din + d];
        float x  = g_xc[(size_t)r * Din + d];
        float Bv = g_Bm[(size_t)r * Nst + n];
        float dA = __expf(a * Aneg);
        p *= dA;
        h = fmaf(dA, h, a * Bv * x);
    }
    g_P[tid] = p;
    g_S[tid] = h;
}

__global__ void scan2_k()
{
    int tid = blockIdx.x * blockDim.x + threadIdx.x;
    if (tid >= Bsz * Din * Nst) return;
    int n = tid & 15;
    int d = (tid >> 4) % Din;
    int b = tid / (Nst * Din);
    float h = 0.f;
    for (int c = 0; c < NCH; c++) {
        int idx = ((b * NCH + c) * Din + d) * Nst + n;
        g_h0[idx] = h;
        h = fmaf(g_P[idx], h, g_S[idx]);
    }
}

__global__ void scan3_k(const float* __restrict__ A_log,
                        const float* __restrict__ Dvec)
{
    int tid = blockIdx.x * blockDim.x + threadIdx.x;
    const int TOT = Bsz * NCH * Din * Nst;
    if (tid >= TOT) return;
    int n = tid & 15;
    int d = (tid >> 4) % Din;
    int c = (tid / (Nst * Din)) % NCH;
    int b = tid / (Nst * Din * NCH);

    float Aneg = -__expf(A_log[d * Nst + n]);
    float h = g_h0[tid];
    float Dd = Dvec[d];
    int rbase = b * Lseq + c * LCH;

    for (int t = 0; t < LCH; t++) {
        int r = rbase + t;
        float a  = g_delta[(size_t)r * Din + d];
        float x  = g_xc[(size_t)r * Din + d];
        float Bv = g_Bm[(size_t)r * Nst + n];
        float Cv = g_Cm[(size_t)r * Nst + n];
        float dA = __expf(a * Aneg);
        h = fmaf(dA, h, a * Bv * x);
        float p = h * Cv;
        p += __shfl_xor_sync(0xffffffffu, p, 8);
        p += __shfl_xor_sync(0xffffffffu, p, 4);
        p += __shfl_xor_sync(0xffffffffu, p, 2);
        p += __shfl_xor_sync(0xffffffffu, p, 1);
        if (n == 0) {
            float z = g_xz[(size_t)r * 384 + 192 + d];
            float yy = p + x * Dd;
            g_y[(size_t)r * Din + d] = yy * (z / (1.f + __expf(-z)));
        }
    }
}

// ---------------- launch ----------------------------------------------------
extern "C" void kernel_launch(void* const* d_in, const int* in_sizes, int n_in,
                              void* d_out, int out_size)
{
    const float* x      = (const float*)d_in[0];
    const float* W_in   = (const float*)d_in[1];
    const float* conv_w = (const float*)d_in[2];
    const float* conv_b = (const float*)d_in[3];
    const float* W_x    = (const float*)d_in[4];
    const float* W_dt   = (const float*)d_in[5];
    const float* b_dt   = (const float*)d_in[6];
    const float* A_log  = (const float*)d_in[7];
    const float* Dvec   = (const float*)d_in[8];
    const float* W_out  = (const float*)d_in[9];
    float* out = (float*)d_out;

    // 1) xz = u @ W_in^T   (M=18432, N=384, K=96)
    gemm_k<0><<<dim3(384 / GBN, Mrows / GBM), 256>>>(x, W_in, nullptr, nullptr,
                                                     Mrows, 384, 96);
    // 2) xc = silu(causal depthwise conv(xs) + b)
    conv_silu_k<<<(Mrows * Din + 255) / 256, 256>>>(conv_w, conv_b);
    // 3) fused projection weight
    build_wcat_k<<<(224 * 192 + 255) / 256, 256>>>(W_x, W_dt);
    // 4) [B | C | delta_pre] = xc @ Wcat^T ; epilogue splits + softplus
    gemm_k<1><<<dim3((224 + GBN - 1) / GBN, Mrows / GBM), 256>>>(
        nullptr, nullptr, b_dt, nullptr, Mrows, 224, 192);
    // 5-7) chunked selective scan (+ D skip + z gate fused in pass 3)
    scan1_k<<<(Bsz * NCH * Din * Nst) / 256, 256>>>(A_log);
    scan2_k<<<(Bsz * Din * Nst + 255) / 256, 256>>>();
    scan3_k<<<(Bsz * NCH * Din * Nst) / 256, 256>>>(A_log, Dvec);
    // 8) out = y @ W_out^T  (N=96, K=192)
    gemm_k<2><<<dim3((96 + GBN - 1) / GBN, Mrows / GBM), 256>>>(
        nullptr, W_out, nullptr, out, Mrows, 96, 192);
}